// round 7
// baseline (speedup 1.0000x reference)
#include <cuda_runtime.h>
#include <cstdint>

// Embedding gather: out[i, :] = w[x[i], :]
// x: [N=16384] int32, w: [32000, 1024] f32, out: [N, 1024] f32.
//
// R6 changes vs R3 (which failed ptxas):
//  - sm_103a requires 256-bit vectors for .L2::evict_last -> use
//    ld.global.nc.L2::evict_last.v4.b64 (32B LDG.256) for the w gather.
//    Pins the ~128MB table in the ~126MB L2; halves load-instruction count.
//  - stores remain evict-first streaming (__stcs, 16B x2 per chunk) so the
//    output stream never displaces w.
//  - block = 128 threads; each thread owns one 32B chunk of the row
//    (128 chunks per 4KB row); 4 rows per block -> 128B in flight/thread.

#define DIM 1024
#define ROW_BYTES (DIM * 4)             // 4096
#define CHUNKS_PER_ROW (ROW_BYTES / 32) // 128
#define THREADS 128
#define ROWS_PER_BLOCK 4

struct Chunk32 { uint64_t a, b, c, d; };

__device__ __forceinline__ Chunk32 ldg_el_32B(const char* p) {
    Chunk32 v;
    asm volatile("ld.global.nc.L2::evict_last.v4.b64 {%0,%1,%2,%3}, [%4];"
                 : "=l"(v.a), "=l"(v.b), "=l"(v.c), "=l"(v.d)
                 : "l"(p));
    return v;
}

__device__ __forceinline__ void stcs_32B(char* p, const Chunk32& v) {
    asm volatile("st.global.cs.v2.b64 [%0], {%1,%2};" :: "l"(p), "l"(v.a), "l"(v.b) : "memory");
    asm volatile("st.global.cs.v2.b64 [%0], {%1,%2};" :: "l"(p + 16), "l"(v.c), "l"(v.d) : "memory");
}

__global__ __launch_bounds__(THREADS)
void embed_gather_kernel(const int* __restrict__ x,
                         const char* __restrict__ w,
                         char* __restrict__ out,
                         int n_rows)
{
    const int tid = threadIdx.x;                 // chunk index within row
    const int row0 = blockIdx.x * ROWS_PER_BLOCK;
    const size_t chunk_off = (size_t)tid * 32;

    if (row0 + ROWS_PER_BLOCK <= n_rows) {
        int idx[ROWS_PER_BLOCK];
#pragma unroll
        for (int r = 0; r < ROWS_PER_BLOCK; r++)
            idx[r] = __ldg(&x[row0 + r]);

        Chunk32 v[ROWS_PER_BLOCK];
#pragma unroll
        for (int r = 0; r < ROWS_PER_BLOCK; r++)
            v[r] = ldg_el_32B(w + (size_t)idx[r] * ROW_BYTES + chunk_off);

#pragma unroll
        for (int r = 0; r < ROWS_PER_BLOCK; r++)
            stcs_32B(out + (size_t)(row0 + r) * ROW_BYTES + chunk_off, v[r]);
    } else {
        for (int r = 0; r < ROWS_PER_BLOCK; r++) {
            int row = row0 + r;
            if (row < n_rows) {
                int idx = __ldg(&x[row]);
                Chunk32 v = ldg_el_32B(w + (size_t)idx * ROW_BYTES + chunk_off);
                stcs_32B(out + (size_t)row * ROW_BYTES + chunk_off, v);
            }
        }
    }
}

extern "C" void kernel_launch(void* const* d_in, const int* in_sizes, int n_in,
                              void* d_out, int out_size)
{
    // metadata order: x (int32, B*S = 16384), w (float32, 32000*1024)
    const int* x = (const int*)d_in[0];
    const char* w = (const char*)d_in[1];
    char* out = (char*)d_out;

    const int n_rows = in_sizes[0];              // 16384
    const int grid = (n_rows + ROWS_PER_BLOCK - 1) / ROWS_PER_BLOCK;

    embed_gather_kernel<<<grid, THREADS>>>(x, w, out, n_rows);
}

// round 8
// speedup vs baseline: 1.0102x; 1.0102x over previous
#include <cuda_runtime.h>
#include <cstdint>

// Embedding gather: out[i, :] = w[x[i], :]
// x: [N=16384] int32, w: [32000, 1024] f32, out: [N, 1024] f32.
//
// R7: R2's shape (256 threads, 8 rows/block, evict-first 16B stores) but the
// w gather uses 256-bit loads (ld.global.nc.v4.b64): half the LDG count,
// 128B in flight per thread at higher occupancy than R2.
//   - block = 2 half-blocks of 128 threads; half h owns rows row0+4h..row0+4h+3
//   - each thread owns one 32B chunk (128 chunks per 4KB row)

#define ROW_BYTES 4096
#define THREADS 256
#define ROWS_PER_HALF 4
#define ROWS_PER_BLOCK (2 * ROWS_PER_HALF)   // 8

struct Chunk32 { uint64_t a, b, c, d; };

__device__ __forceinline__ Chunk32 ldg_nc_32B(const char* p) {
    Chunk32 v;
    asm volatile("ld.global.nc.v4.b64 {%0,%1,%2,%3}, [%4];"
                 : "=l"(v.a), "=l"(v.b), "=l"(v.c), "=l"(v.d)
                 : "l"(p));
    return v;
}

__device__ __forceinline__ void stcs_32B(char* p, const Chunk32& v) {
    asm volatile("st.global.cs.v2.b64 [%0], {%1,%2};"
                 :: "l"(p), "l"(v.a), "l"(v.b) : "memory");
    asm volatile("st.global.cs.v2.b64 [%0], {%1,%2};"
                 :: "l"(p + 16), "l"(v.c), "l"(v.d) : "memory");
}

__global__ __launch_bounds__(THREADS)
void embed_gather_kernel(const int* __restrict__ x,
                         const char* __restrict__ w,
                         char* __restrict__ out,
                         int n_rows)
{
    const int tid   = threadIdx.x;
    const int half  = tid >> 7;              // 0 or 1
    const int ctid  = tid & 127;             // chunk index within row
    const size_t chunk_off = (size_t)ctid * 32;

    const int row0 = blockIdx.x * ROWS_PER_BLOCK + half * ROWS_PER_HALF;

    if (row0 + ROWS_PER_HALF <= n_rows) {
        int idx[ROWS_PER_HALF];
#pragma unroll
        for (int r = 0; r < ROWS_PER_HALF; r++)
            idx[r] = __ldg(&x[row0 + r]);

        Chunk32 v[ROWS_PER_HALF];
#pragma unroll
        for (int r = 0; r < ROWS_PER_HALF; r++)
            v[r] = ldg_nc_32B(w + (size_t)idx[r] * ROW_BYTES + chunk_off);

#pragma unroll
        for (int r = 0; r < ROWS_PER_HALF; r++)
            stcs_32B(out + (size_t)(row0 + r) * ROW_BYTES + chunk_off, v[r]);
    } else {
        for (int r = 0; r < ROWS_PER_HALF; r++) {
            int row = row0 + r;
            if (row < n_rows) {
                int idx = __ldg(&x[row]);
                Chunk32 v = ldg_nc_32B(w + (size_t)idx * ROW_BYTES + chunk_off);
                stcs_32B(out + (size_t)row * ROW_BYTES + chunk_off, v);
            }
        }
    }
}

extern "C" void kernel_launch(void* const* d_in, const int* in_sizes, int n_in,
                              void* d_out, int out_size)
{
    // metadata order: x (int32, B*S = 16384), w (float32, 32000*1024)
    const int* x = (const int*)d_in[0];
    const char* w = (const char*)d_in[1];
    char* out = (char*)d_out;

    const int n_rows = in_sizes[0];              // 16384
    const int grid = (n_rows + ROWS_PER_BLOCK - 1) / ROWS_PER_BLOCK;

    embed_gather_kernel<<<grid, THREADS>>>(x, w, out, n_rows);
}

// round 9
// speedup vs baseline: 1.1913x; 1.1792x over previous
#include <cuda_runtime.h>
#include <cstdint>

// Embedding gather: out[i, :] = w[x[i], :]
// x: [N=16384] int32, w: [32000, 1024] f32, out: [N, 1024] f32.
//
// R8 theory: steady-state (graph replay) was DRAM-WRITE bound at ~4 TB/s
// (67MB output rewritten every replay). Invert the L2 residency policy:
//  - stores: st.global.L2::evict_last (32B v4.b64 - hint requires 256-bit)
//    -> output stays dirty-resident in L2; rewrites of resident dirty lines
//       produce NO DRAM writebacks across replays.
//  - loads: plain float4 ld.global.nc (evict-normal). w fills churn in the
//    unpinned remainder of L2 and cannot displace the pinned output.
// Loads keep R2's proven structure: 8 independent 16B loads batched before
// any store (R6/R7 failed because 32B LOADS blew the reg budget and ptxas
// serialized load->store; 32B STORES are issue-only and safe).

#define ROW_BYTES 4096
#define THREADS 256
#define ROWS_PER_HALF 4
#define ROWS_PER_BLOCK (2 * ROWS_PER_HALF)   // 8

__device__ __forceinline__ void st_el_32B(char* p, float4 lo, float4 hi) {
    asm volatile("st.global.L2::evict_last.v4.b64 [%0], {%1,%2,%3,%4};"
                 :: "l"(p),
                    "l"(*(const uint64_t*)&lo.x), "l"(*(const uint64_t*)&lo.z),
                    "l"(*(const uint64_t*)&hi.x), "l"(*(const uint64_t*)&hi.z)
                 : "memory");
}

__global__ __launch_bounds__(THREADS)
void embed_gather_kernel(const int* __restrict__ x,
                         const char* __restrict__ w,
                         char* __restrict__ out,
                         int n_rows)
{
    const int tid  = threadIdx.x;
    const int half = tid >> 7;               // 0 or 1
    const int ctid = tid & 127;              // 32B-chunk index within row
    const size_t chunk_off = (size_t)ctid * 32;

    const int row0 = blockIdx.x * ROWS_PER_BLOCK + half * ROWS_PER_HALF;

    if (row0 + ROWS_PER_HALF <= n_rows) {
        int idx[ROWS_PER_HALF];
#pragma unroll
        for (int r = 0; r < ROWS_PER_HALF; r++)
            idx[r] = __ldg(&x[row0 + r]);

        // 8 independent 16B loads, all issued before any store (MLP).
        float4 lo[ROWS_PER_HALF], hi[ROWS_PER_HALF];
#pragma unroll
        for (int r = 0; r < ROWS_PER_HALF; r++) {
            const float4* src =
                (const float4*)(w + (size_t)idx[r] * ROW_BYTES + chunk_off);
            lo[r] = __ldg(src);
            hi[r] = __ldg(src + 1);
        }

#pragma unroll
        for (int r = 0; r < ROWS_PER_HALF; r++)
            st_el_32B(out + (size_t)(row0 + r) * ROW_BYTES + chunk_off,
                      lo[r], hi[r]);
    } else {
        for (int r = 0; r < ROWS_PER_HALF; r++) {
            int row = row0 + r;
            if (row < n_rows) {
                int idx = __ldg(&x[row]);
                const float4* src =
                    (const float4*)(w + (size_t)idx * ROW_BYTES + chunk_off);
                float4 lo = __ldg(src);
                float4 hi = __ldg(src + 1);
                st_el_32B(out + (size_t)row * ROW_BYTES + chunk_off, lo, hi);
            }
        }
    }
}

extern "C" void kernel_launch(void* const* d_in, const int* in_sizes, int n_in,
                              void* d_out, int out_size)
{
    // metadata order: x (int32, B*S = 16384), w (float32, 32000*1024)
    const int* x = (const int*)d_in[0];
    const char* w = (const char*)d_in[1];
    char* out = (char*)d_out;

    const int n_rows = in_sizes[0];              // 16384
    const int grid = (n_rows + ROWS_PER_BLOCK - 1) / ROWS_PER_BLOCK;

    embed_gather_kernel<<<grid, THREADS>>>(x, w, out, n_rows);
}

// round 10
// speedup vs baseline: 1.2058x; 1.0122x over previous
#include <cuda_runtime.h>
#include <cstdint>

// Embedding gather: out[i, :] = w[x[i], :]
// x: [N=16384] int32, w: [32000, 1024] f32, out: [N, 1024] f32.
//
// R9 theory: steady-state is DRAM-WRITE bound (~64MiB writes @ ~4TB/s =
// 16.9us). Total working set exceeds L2 by ~66MB, so ~66MB/replay of DRAM
// traffic is forced -- but the DIRECTION is our choice. Flip it:
//  - w loads:  __ldcs (ld.global.cs, evict-first streaming at 16B -- avoids
//    the 32B-load register trap from R6/R7). w never competes for L2.
//  - out stores: plain evict-normal stores that ALLOCATE in L2. Output
//    (64MB) is then the only evict-normal data and fits in 126MB L2 ->
//    stays dirty-resident across graph replays -> steady-state DRAM writes
//    ~0; DRAM traffic becomes ~64MB of READS (the faster direction).
// Structure is exactly R2's proven shape: 256 thr, 8 rows/block, 8 batched
// independent 16B loads before any store.

#define DIM 1024
#define VECS_PER_ROW (DIM / 4)      // 256 float4 per row
#define THREADS 256
#define ROWS_PER_BLOCK 8

__global__ __launch_bounds__(THREADS)
void embed_gather_kernel(const int* __restrict__ x,
                         const float4* __restrict__ w,
                         float4* __restrict__ out,
                         int n_rows)
{
    const int tid = threadIdx.x;              // vec index within row
    const int row0 = blockIdx.x * ROWS_PER_BLOCK;

    if (row0 + ROWS_PER_BLOCK <= n_rows) {
        int idx[ROWS_PER_BLOCK];
#pragma unroll
        for (int r = 0; r < ROWS_PER_BLOCK; r++)
            idx[r] = __ldg(&x[row0 + r]);

        // 8 independent streaming (evict-first) loads, batched for MLP.
        float4 v[ROWS_PER_BLOCK];
#pragma unroll
        for (int r = 0; r < ROWS_PER_BLOCK; r++)
            v[r] = __ldcs(&w[(size_t)idx[r] * VECS_PER_ROW + tid]);

        // Plain evict-normal stores: allocate output in L2, let LRU keep it.
#pragma unroll
        for (int r = 0; r < ROWS_PER_BLOCK; r++)
            out[(size_t)(row0 + r) * VECS_PER_ROW + tid] = v[r];
    } else {
        for (int r = 0; r < ROWS_PER_BLOCK; r++) {
            int row = row0 + r;
            if (row < n_rows) {
                int idx = __ldg(&x[row]);
                float4 v = __ldcs(&w[(size_t)idx * VECS_PER_ROW + tid]);
                out[(size_t)row * VECS_PER_ROW + tid] = v;
            }
        }
    }
}

extern "C" void kernel_launch(void* const* d_in, const int* in_sizes, int n_in,
                              void* d_out, int out_size)
{
    // metadata order: x (int32, B*S = 16384), w (float32, 32000*1024)
    const int* x = (const int*)d_in[0];
    const float4* w = (const float4*)d_in[1];
    float4* out = (float4*)d_out;

    const int n_rows = in_sizes[0];           // 16384
    const int grid = (n_rows + ROWS_PER_BLOCK - 1) / ROWS_PER_BLOCK;

    embed_gather_kernel<<<grid, THREADS>>>(x, w, out, n_rows);
}

// round 11
// speedup vs baseline: 1.5009x; 1.2448x over previous
#include <cuda_runtime.h>
#include <cstdint>

// Embedding gather: out[i, :] = w[x[i], :]
// x: [N=16384] int32, w: [32000, 1024] f32, out: [N, 1024] f32.
//
// R10 = R2 (best: 16.9us) with doubled per-block row count.
// Established by R1/R2/R6/R8/R9:
//  - __stcs evict-first stores are the key win: they keep the ~128MB w table
//    L2-resident across graph replays (reads become L2 hits), leaving the
//    mandatory 64MiB of output DRAM writes as the binding resource (~4TB/s).
//  - Output cannot be pinned in L2 (persisting-carveout is 0 and changing
//    device limits is banned), so eviction-hint schemes are inert/harmful.
//  - Loads must stay 16B __ldg, batched 8-at-a-time before any store
//    (32B loads blow the reg budget and ptxas serializes -> MLP collapse).
// R10 lever: ROWS_PER_BLOCK 16 via two batches of 8 -> 64KB contiguous
// output per block (better DRAM write-page locality / LTS queueing), same
// proven per-batch register and MLP profile.

#define DIM 1024
#define VECS_PER_ROW (DIM / 4)      // 256 float4 per row
#define THREADS 256
#define BATCH 8
#define ROWS_PER_BLOCK 16           // two batches of 8

__device__ __forceinline__ void do_batch(const int* __restrict__ x,
                                         const float4* __restrict__ w,
                                         float4* __restrict__ out,
                                         int row0, int tid)
{
    int idx[BATCH];
#pragma unroll
    for (int r = 0; r < BATCH; r++)
        idx[r] = __ldg(&x[row0 + r]);

    // 8 independent 16B gather loads, all issued before any store (MLP).
    float4 v[BATCH];
#pragma unroll
    for (int r = 0; r < BATCH; r++)
        v[r] = __ldg(&w[(size_t)idx[r] * VECS_PER_ROW + tid]);

    // Evict-first streaming stores: never displace w from L2.
#pragma unroll
    for (int r = 0; r < BATCH; r++)
        __stcs(&out[(size_t)(row0 + r) * VECS_PER_ROW + tid], v[r]);
}

__global__ __launch_bounds__(THREADS)
void embed_gather_kernel(const int* __restrict__ x,
                         const float4* __restrict__ w,
                         float4* __restrict__ out,
                         int n_rows)
{
    const int tid = threadIdx.x;              // vec index within row
    const int row0 = blockIdx.x * ROWS_PER_BLOCK;

    if (row0 + ROWS_PER_BLOCK <= n_rows) {
        do_batch(x, w, out, row0, tid);
        do_batch(x, w, out, row0 + BATCH, tid);
    } else {
        for (int r = 0; r < ROWS_PER_BLOCK; r++) {
            int row = row0 + r;
            if (row < n_rows) {
                int idx = __ldg(&x[row]);
                float4 v = __ldg(&w[(size_t)idx * VECS_PER_ROW + tid]);
                __stcs(&out[(size_t)row * VECS_PER_ROW + tid], v);
            }
        }
    }
}

extern "C" void kernel_launch(void* const* d_in, const int* in_sizes, int n_in,
                              void* d_out, int out_size)
{
    // metadata order: x (int32, B*S = 16384), w (float32, 32000*1024)
    const int* x = (const int*)d_in[0];
    const float4* w = (const float4*)d_in[1];
    float4* out = (float4*)d_out;

    const int n_rows = in_sizes[0];           // 16384
    const int grid = (n_rows + ROWS_PER_BLOCK - 1) / ROWS_PER_BLOCK;

    embed_gather_kernel<<<grid, THREADS>>>(x, w, out, n_rows);
}